// round 1
// baseline (speedup 1.0000x reference)
#include <cuda_runtime.h>

// Conv_RBS_density: rho_out = M rho M^T where M = product of 48 RBS (Givens)
// layers on the Hamming-weight-2 basis (N = C(32,2) = 496 pairs, lexicographic).
// Each gate on adjacent qubits (i, i+1) rotates row/col pairs
//   s = idx(sorted(i,c)), q = idx(sorted(i+1,c))  for each spectator c:
//   new_s = cos*s + sin*q ; new_q = cos*q - sin*s
// Phase 0 (row): Y = M rho, blocks own 4-column slices.
// Phase 1 (col): out = Y M^T, blocks own 4-row slices (in-place on d_out).

#define NPAIRS 496
#define NGATES 48
#define NPARAMS 12
#define CPB 4          // columns (or rows) per block
#define NBLOCKS (NPAIRS / CPB)

__device__ __forceinline__ int pair_idx(int a, int b) {
    // a < b, n = 32 qubits; lexicographic pair index
    return a * 31 - (a * (a - 1)) / 2 + (b - a - 1);
}

template <int PHASE>
__global__ void __launch_bounds__(128, 1)
rbs_phase(const float* __restrict__ src, float* __restrict__ dst,
          const float* __restrict__ thetas,
          const int* __restrict__ u_idx, const int* __restrict__ p_idx)
{
    __shared__ float tile[NPAIRS * CPB];
    __shared__ float cosv[NPARAMS], sinv[NPARAMS];
    __shared__ int   gI[NGATES];
    __shared__ float gC[NGATES], gS[NGATES];

    const int tid  = threadIdx.x;
    const int base = blockIdx.x * CPB;

    if (tid < NPARAMS) {
        float s, c;
        sincosf(thetas[tid], &s, &c);
        cosv[tid] = c; sinv[tid] = s;
    }
    __syncthreads();
    if (tid < NGATES) {
        int u = u_idx[tid];
        gI[tid] = (u / 3) * 4 + (u % 3);   // unique tuple -> lower qubit i
        int p = p_idx[tid];
        gC[tid] = cosv[p]; gS[tid] = sinv[p];
    }

    // Load slice into shared: layout tile[pair*4 + k]
    if (PHASE == 0) {
        // block owns columns [base, base+4): strided float4 gathers
        for (int r = tid; r < NPAIRS; r += 128) {
            float4 v = *reinterpret_cast<const float4*>(src + r * NPAIRS + base);
            tile[r * 4 + 0] = v.x; tile[r * 4 + 1] = v.y;
            tile[r * 4 + 2] = v.z; tile[r * 4 + 3] = v.w;
        }
    } else {
        // block owns rows [base, base+4): coalesced row loads
        #pragma unroll
        for (int k = 0; k < CPB; k++)
            for (int c = tid; c < NPAIRS; c += 128)
                tile[c * 4 + k] = src[(base + k) * NPAIRS + c];
    }
    __syncthreads();

    const int m = tid >> 2;      // spectator slot 0..29
    const int k = tid & 3;       // slice lane 0..3
    const bool act = (tid < 120);

    #pragma unroll 4
    for (int g = 0; g < NGATES; g++) {
        if (act) {
            const int i   = gI[g];
            const float co = gC[g], si = gS[g];
            const int c = m + (m >= i ? 2 : 0);   // skip qubits i, i+1
            const int j = i + 1;
            const int a1 = min(i, c), b1 = max(i, c);
            const int a2 = min(j, c), b2 = max(j, c);
            const int s = pair_idx(a1, b1);       // pair containing i
            const int q = pair_idx(a2, b2);       // pair containing j
            const float x = tile[s * 4 + k];
            const float y = tile[q * 4 + k];
            tile[s * 4 + k] = co * x + si * y;
            tile[q * 4 + k] = co * y - si * x;
        }
        __syncthreads();
    }

    if (PHASE == 0) {
        for (int r = tid; r < NPAIRS; r += 128) {
            float4 v = make_float4(tile[r * 4 + 0], tile[r * 4 + 1],
                                   tile[r * 4 + 2], tile[r * 4 + 3]);
            *reinterpret_cast<float4*>(dst + r * NPAIRS + base) = v;
        }
    } else {
        #pragma unroll
        for (int k2 = 0; k2 < CPB; k2++)
            for (int c = tid; c < NPAIRS; c += 128)
                dst[(base + k2) * NPAIRS + c] = tile[c * 4 + k2];
    }
}

extern "C" void kernel_launch(void* const* d_in, const int* in_sizes, int n_in,
                              void* d_out, int out_size) {
    // metadata order: rho, thetas, A_stack, B_stack, C_stack, u_idx, p_idx
    const float* rho    = (const float*)d_in[0];
    const float* thetas = (const float*)d_in[1];
    const int*   u_idx  = (const int*)d_in[5];
    const int*   p_idx  = (const int*)d_in[6];
    float* out = (float*)d_out;

    // Phase 0: out = M * rho      (row rotations, blocks over column slices)
    rbs_phase<0><<<NBLOCKS, 128>>>(rho, out, thetas, u_idx, p_idx);
    // Phase 1: out = out * M^T    (col rotations, blocks over row slices, in place)
    rbs_phase<1><<<NBLOCKS, 128>>>(out, out, thetas, u_idx, p_idx);
}

// round 2
// speedup vs baseline: 1.1616x; 1.1616x over previous
#include <cuda_runtime.h>

// Conv_RBS_density: out = M rho M^T on the Hamming-weight-2 basis of 32 qubits
// (N = C(32,2) = 496, lexicographic pairs). The 48 RBS gates live in 8 disjoint
// 4-qubit tiles, so M = Lambda^2(U) with U = diag(V_0..V_7), V_t 4x4 orthogonal.
// In the pair basis M is block diagonal:
//   cross-tile block (t1<t2): 16-dim, B = V_t1 (x) V_t2
//   within-tile block (t):     6-dim, B = Lambda^2(V_t)
// => out[I,J] = B_I rho[I,J] B_J^T : every block-row is independent.
// One kernel, grid = 36 row blocks, block = 256 threads.

#define NP 496
#define SL 500   // padded slab stride

__device__ __forceinline__ int pair_idx(int a, int b) {
    // a < b, 32 qubits, lexicographic
    return a * 31 - (a * (a - 1)) / 2 + (b - a - 1);
}

__device__ __forceinline__ void decode_block(int B, int& t1, int& t2, int& dim) {
    if (B < 28) {
        int rem = B, a = 0;
        while (rem >= 7 - a) { rem -= 7 - a; a++; }
        t1 = a; t2 = a + 1 + rem; dim = 16;
    } else {
        t1 = B - 28; t2 = t1; dim = 6;
    }
}

__global__ void __launch_bounds__(256, 1)
rbs_block_kernel(const float* __restrict__ rho, float* __restrict__ out,
                 const float* __restrict__ thetas,
                 const int* __restrict__ u_idx, const int* __restrict__ p_idx)
{
    __shared__ float slab[16 * SL];
    __shared__ float V[8][4][4];
    __shared__ float W[8][6][6];
    __shared__ int   grow[16];
    __shared__ float cs[12], sn[12];

    const int tid = threadIdx.x;

    if (tid < 12) {
        float s, c;
        sincosf(thetas[tid], &s, &c);
        cs[tid] = c; sn[tid] = s;
    }
    __syncthreads();

    // Build per-tile 4x4 V by composing the gate stream (threads 0..7).
    if (tid < 8) {
        float v[4][4];
        #pragma unroll
        for (int r = 0; r < 4; r++)
            #pragma unroll
            for (int c = 0; c < 4; c++) v[r][c] = (r == c) ? 1.f : 0.f;
        for (int g = 0; g < 48; g++) {
            int u = u_idx[g];
            int q = (u / 3) * 4 + (u % 3);   // unique-tuple -> lower qubit
            if ((q >> 2) == tid) {
                int li = q & 3;
                int p  = p_idx[g];
                float c = cs[p], s = sn[p];
                #pragma unroll
                for (int k = 0; k < 4; k++) {
                    float a = v[li][k], b = v[li + 1][k];
                    v[li][k]     = c * a + s * b;
                    v[li + 1][k] = c * b - s * a;
                }
            }
        }
        #pragma unroll
        for (int r = 0; r < 4; r++)
            #pragma unroll
            for (int c = 0; c < 4; c++) V[tid][r][c] = v[r][c];
    }
    __syncthreads();

    // W_t = Lambda^2(V_t): 8 * 36 entries
    {
        const int P1[6] = {0,0,0,1,1,2}, P2[6] = {1,2,3,2,3,3};
        for (int e = tid; e < 288; e += 256) {
            int t = e / 36, mn = e % 36, m = mn / 6, n = mn % 6;
            int a = P1[m], b = P2[m], g = P1[n], d = P2[n];
            W[t][m][n] = V[t][a][g] * V[t][b][d] - V[t][a][d] * V[t][b][g];
        }
    }

    // Decode this CTA's row block, fill global row indices.
    int T1, T2, DI;
    decode_block(blockIdx.x, T1, T2, DI);
    if (tid < DI) {
        int a, b;
        if (DI == 16) { a = 4 * T1 + (tid >> 2); b = 4 * T2 + (tid & 3); }
        else {
            const int P1[6] = {0,0,0,1,1,2}, P2[6] = {1,2,3,2,3,3};
            a = 4 * T1 + P1[tid]; b = 4 * T1 + P2[tid];
        }
        grow[tid] = pair_idx(a, b);
    }
    __syncthreads();

    // ---- LEFT: slab = B_I * rho[rows of I, :]  (per column, in registers) ----
    for (int c = tid; c < NP; c += 256) {
        if (DI == 16) {
            float X[16];
            #pragma unroll
            for (int m = 0; m < 16; m++) X[m] = rho[grow[m] * NP + c];
            float tmp[16];
            #pragma unroll
            for (int al = 0; al < 4; al++)
                #pragma unroll
                for (int bp = 0; bp < 4; bp++) {
                    float acc = 0.f;
                    #pragma unroll
                    for (int ap = 0; ap < 4; ap++) acc += V[T1][al][ap] * X[ap * 4 + bp];
                    tmp[al * 4 + bp] = acc;
                }
            #pragma unroll
            for (int al = 0; al < 4; al++)
                #pragma unroll
                for (int be = 0; be < 4; be++) {
                    float acc = 0.f;
                    #pragma unroll
                    for (int bp = 0; bp < 4; bp++) acc += V[T2][be][bp] * tmp[al * 4 + bp];
                    slab[(al * 4 + be) * SL + c] = acc;
                }
        } else {
            float X[6];
            #pragma unroll
            for (int m = 0; m < 6; m++) X[m] = rho[grow[m] * NP + c];
            #pragma unroll
            for (int m = 0; m < 6; m++) {
                float acc = 0.f;
                #pragma unroll
                for (int n = 0; n < 6; n++) acc += W[T1][m][n] * X[n];
                slab[m * SL + c] = acc;
            }
        }
    }
    __syncthreads();

    // ---- RIGHT: for each (col block J, row r): slab cols of J <- B_J * y ----
    const int TT = 36 * DI;
    for (int task = tid; task < TT; task += 256) {
        int J = task / DI, r = task % DI;
        int t1, t2, dj;
        decode_block(J, t1, t2, dj);
        if (dj == 16) {
            int col[16];
            #pragma unroll
            for (int m = 0; m < 16; m++)
                col[m] = pair_idx(4 * t1 + (m >> 2), 4 * t2 + (m & 3));
            float Y[16];
            #pragma unroll
            for (int m = 0; m < 16; m++) Y[m] = slab[r * SL + col[m]];
            float tmp[16];
            #pragma unroll
            for (int ga = 0; ga < 4; ga++)
                #pragma unroll
                for (int dp = 0; dp < 4; dp++) {
                    float acc = 0.f;
                    #pragma unroll
                    for (int gp = 0; gp < 4; gp++) acc += V[t1][ga][gp] * Y[gp * 4 + dp];
                    tmp[ga * 4 + dp] = acc;
                }
            #pragma unroll
            for (int ga = 0; ga < 4; ga++)
                #pragma unroll
                for (int de = 0; de < 4; de++) {
                    float acc = 0.f;
                    #pragma unroll
                    for (int dp = 0; dp < 4; dp++) acc += V[t2][de][dp] * tmp[ga * 4 + dp];
                    slab[r * SL + col[ga * 4 + de]] = acc;
                }
        } else {
            const int P1[6] = {0,0,0,1,1,2}, P2[6] = {1,2,3,2,3,3};
            int col[6];
            #pragma unroll
            for (int m = 0; m < 6; m++)
                col[m] = pair_idx(4 * t1 + P1[m], 4 * t1 + P2[m]);
            float Y[6];
            #pragma unroll
            for (int m = 0; m < 6; m++) Y[m] = slab[r * SL + col[m]];
            #pragma unroll
            for (int m = 0; m < 6; m++) {
                float acc = 0.f;
                #pragma unroll
                for (int n = 0; n < 6; n++) acc += W[t1][m][n] * Y[n];
                slab[r * SL + col[m]] = acc;
            }
        }
    }
    __syncthreads();

    // ---- STORE: coalesced rows ----
    for (int r = 0; r < DI; r++)
        for (int c = tid; c < NP; c += 256)
            out[grow[r] * NP + c] = slab[r * SL + c];
}

extern "C" void kernel_launch(void* const* d_in, const int* in_sizes, int n_in,
                              void* d_out, int out_size) {
    // metadata order: rho, thetas, A_stack, B_stack, C_stack, u_idx, p_idx
    const float* rho    = (const float*)d_in[0];
    const float* thetas = (const float*)d_in[1];
    const int*   u_idx  = (const int*)d_in[5];
    const int*   p_idx  = (const int*)d_in[6];
    float* out = (float*)d_out;

    rbs_block_kernel<<<36, 256>>>(rho, out, thetas, u_idx, p_idx);
}

// round 3
// speedup vs baseline: 1.2885x; 1.1093x over previous
#include <cuda_runtime.h>

// out = M rho M^T, M block-diagonal in the Hamming-weight-2 pair basis:
//   out[I,J] = B_I rho[I,J] B_J^T  for 36 blocks I,J
//   cross-tile block (t1<t2): dim 16, B = V_t1 (x) V_t2  (Kronecker-factored)
//   diagonal  block (t):      dim 6,  B = Lambda^2(V_t) = W_t
// One CTA per (I,J): grid = 1296, block = 64. Fully parallel, no inter-CTA deps.

#define NP 496

__device__ __forceinline__ int pair_idx(int a, int b) {
    return a * 31 - (a * (a - 1)) / 2 + (b - a - 1);
}

__device__ __forceinline__ void decode_block(int B, int& t1, int& t2, int& dim) {
    if (B < 28) {
        int rem = B, a = 0;
        while (rem >= 7 - a) { rem -= 7 - a; a++; }
        t1 = a; t2 = a + 1 + rem; dim = 16;
    } else {
        t1 = B - 28; t2 = t1; dim = 6;
    }
}

__constant__ int cP1[6] = {0,0,0,1,1,2};
__constant__ int cP2[6] = {1,2,3,2,3,3};

__global__ void __launch_bounds__(64, 16)
rbs_pair_kernel(const float* __restrict__ rho, float* __restrict__ out,
                const float* __restrict__ thetas,
                const int* __restrict__ u_idx, const int* __restrict__ p_idx)
{
    __shared__ float V[8][16];        // per-tile 4x4 (row-major)
    __shared__ float WI[36], WJ[36];  // Lambda^2 for diagonal blocks
    __shared__ float bufA[16][17], bufB[16][17];
    __shared__ int   grow[16], gcol[16];
    __shared__ float cs[12], sn[12];
    __shared__ int   gu[48], gp[48];

    const int tid = threadIdx.x;
    const int I = blockIdx.x / 36, J = blockIdx.x % 36;

    int T1, T2, DI, t1, t2, DJ;
    decode_block(I, T1, T2, DI);
    decode_block(J, t1, t2, DJ);

    // -- stage in gate stream + angles ---------------------------------------
    if (tid < 48) { gu[tid] = u_idx[tid]; gp[tid] = p_idx[tid]; }
    if (tid >= 48 && tid < 60) {
        int p = tid - 48;
        float s, c; sincosf(thetas[p], &s, &c);
        cs[p] = c; sn[p] = s;
    }
    // row / col global pair indices (independent of V)
    if (tid < 16 && tid < DI) {
        int a, b;
        if (DI == 16) { a = 4 * T1 + (tid >> 2); b = 4 * T2 + (tid & 3); }
        else          { a = 4 * T1 + cP1[tid];   b = 4 * T1 + cP2[tid]; }
        grow[tid] = pair_idx(a, b);
    }
    if (tid >= 32 && tid - 32 < DJ) {
        int m = tid - 32, a, b;
        if (DJ == 16) { a = 4 * t1 + (m >> 2); b = 4 * t2 + (m & 3); }
        else          { a = 4 * t1 + cP1[m];   b = 4 * t1 + cP2[m]; }
        gcol[m] = pair_idx(a, b);
    }
    __syncthreads();

    // -- compose per-tile V (threads 0..7, one tile each) --------------------
    if (tid < 8) {
        float v[4][4];
        #pragma unroll
        for (int r = 0; r < 4; r++)
            #pragma unroll
            for (int c = 0; c < 4; c++) v[r][c] = (r == c) ? 1.f : 0.f;
        #pragma unroll 8
        for (int g = 0; g < 48; g++) {
            int u = gu[g];
            int q = (u / 3) * 4 + (u % 3);       // unique tuple -> lower qubit
            if ((q >> 2) == tid) {
                int li = q & 3, p = gp[g];
                float c = cs[p], s = sn[p];
                #pragma unroll
                for (int k = 0; k < 4; k++) {
                    float a = v[li][k], b = v[li + 1][k];
                    v[li][k]     = c * a + s * b;
                    v[li + 1][k] = c * b - s * a;
                }
            }
        }
        #pragma unroll
        for (int r = 0; r < 4; r++)
            #pragma unroll
            for (int c = 0; c < 4; c++) V[tid][r * 4 + c] = v[r][c];
    }
    __syncthreads();

    // -- W for diagonal blocks (always compute; cheap) + load rho block ------
    for (int e = tid; e < 72; e += 64) {
        int side = e / 36, mn = e % 36, m = mn / 6, n = mn % 6;
        int t = side ? t1 : T1;
        int a = cP1[m], b = cP2[m], g = cP1[n], d = cP2[n];
        float w = V[t][a * 4 + g] * V[t][b * 4 + d]
                - V[t][a * 4 + d] * V[t][b * 4 + g];
        if (side) WJ[mn] = w; else WI[mn] = w;
    }
    for (int e = tid; e < DI * DJ; e += 64) {
        int m = e / DJ, c = e % DJ;
        bufA[m][c] = rho[grow[m] * NP + gcol[c]];
    }
    __syncthreads();

    float (*cur)[17] = bufA;
    float (*nxt)[17] = bufB;

    // -- LEFT: cur <- B_I * cur ----------------------------------------------
    if (DI == 16) {
        // stage 1: (V_T1 (x) I)
        for (int e = tid; e < 16 * DJ; e += 64) {
            int m = e / DJ, c = e % DJ;
            int al = m >> 2, bp = m & 3;
            float acc = 0.f;
            #pragma unroll
            for (int ap = 0; ap < 4; ap++)
                acc += V[T1][al * 4 + ap] * cur[ap * 4 + bp][c];
            nxt[m][c] = acc;
        }
        __syncthreads();
        { float (*t)[17] = cur; cur = nxt; nxt = t; }
        // stage 2: (I (x) V_T2)
        for (int e = tid; e < 16 * DJ; e += 64) {
            int m = e / DJ, c = e % DJ;
            int base = m & ~3, be = m & 3;
            float acc = 0.f;
            #pragma unroll
            for (int bp = 0; bp < 4; bp++)
                acc += V[T2][be * 4 + bp] * cur[base + bp][c];
            nxt[m][c] = acc;
        }
        __syncthreads();
        { float (*t)[17] = cur; cur = nxt; nxt = t; }
    } else {
        for (int e = tid; e < 6 * DJ; e += 64) {
            int m = e / DJ, c = e % DJ;
            float acc = 0.f;
            #pragma unroll
            for (int n = 0; n < 6; n++) acc += WI[m * 6 + n] * cur[n][c];
            nxt[m][c] = acc;
        }
        __syncthreads();
        { float (*t)[17] = cur; cur = nxt; nxt = t; }
    }

    // -- RIGHT: cur <- cur * B_J^T --------------------------------------------
    if (DJ == 16) {
        // stage 1: columns, (V_t1 (x) I)
        for (int e = tid; e < DI * 16; e += 64) {
            int m = e / 16, c = e % 16;
            int ga = c >> 2, dp = c & 3;
            float acc = 0.f;
            #pragma unroll
            for (int gp2 = 0; gp2 < 4; gp2++)
                acc += V[t1][ga * 4 + gp2] * cur[m][gp2 * 4 + dp];
            nxt[m][c] = acc;
        }
        __syncthreads();
        { float (*t)[17] = cur; cur = nxt; nxt = t; }
        // stage 2: (I (x) V_t2)
        for (int e = tid; e < DI * 16; e += 64) {
            int m = e / 16, c = e % 16;
            int base = c & ~3, de = c & 3;
            float acc = 0.f;
            #pragma unroll
            for (int dp = 0; dp < 4; dp++)
                acc += V[t2][de * 4 + dp] * cur[m][base + dp];
            nxt[m][c] = acc;
        }
        __syncthreads();
        { float (*t)[17] = cur; cur = nxt; nxt = t; }
    } else {
        for (int e = tid; e < DI * 6; e += 64) {
            int m = e / 6, c = e % 6;
            float acc = 0.f;
            #pragma unroll
            for (int n = 0; n < 6; n++) acc += WJ[c * 6 + n] * cur[m][n];
            nxt[m][c] = acc;
        }
        __syncthreads();
        { float (*t)[17] = cur; cur = nxt; nxt = t; }
    }

    // -- STORE ----------------------------------------------------------------
    for (int e = tid; e < DI * DJ; e += 64) {
        int m = e / DJ, c = e % DJ;
        out[grow[m] * NP + gcol[c]] = cur[m][c];
    }
}

extern "C" void kernel_launch(void* const* d_in, const int* in_sizes, int n_in,
                              void* d_out, int out_size) {
    // metadata order: rho, thetas, A_stack, B_stack, C_stack, u_idx, p_idx
    const float* rho    = (const float*)d_in[0];
    const float* thetas = (const float*)d_in[1];
    const int*   u_idx  = (const int*)d_in[5];
    const int*   p_idx  = (const int*)d_in[6];
    float* out = (float*)d_out;

    rbs_pair_kernel<<<36 * 36, 64>>>(rho, out, thetas, u_idx, p_idx);
}

// round 4
// speedup vs baseline: 2.6434x; 2.0515x over previous
#include <cuda_runtime.h>

// out = M rho M^T on the Hamming-weight-2 basis (N = C(32,2) = 496).
// M is block-diagonal over 36 pair-blocks; only TWO distinct 4x4 tile
// matrices exist (row-register V_row: params 0-5, col-register V_col: 6-11),
// each a fixed pyramid of 6 Givens with local qubit sequence {0,1,0,2,1,0}.
//   cross block (t1<t2): dim 16, B = V_t1 (x) V_t2
//   diag  block (t):     dim 6,  B = Lambda^2(V_t) = W
// Grid = 36*36 CTAs (one per (I,J) output block), 64 threads.

#define NP 496

__device__ __forceinline__ int pair_idx(int a, int b) {
    return a * 31 - (a * (a - 1)) / 2 + (b - a - 1);
}

__device__ __forceinline__ void decode_block(int B, int& t1, int& t2, int& dim) {
    if (B < 28) {
        int rem = B, a = 0;
        while (rem >= 7 - a) { rem -= 7 - a; a++; }
        t1 = a; t2 = a + 1 + rem; dim = 16;
    } else {
        t1 = B - 28; t2 = t1; dim = 6;
    }
}

// bit-packed pair tables for the 6-dim (diagonal) blocks:
// P1 = {0,0,0,1,1,2}, P2 = {1,2,3,2,3,3}, 3 bits per entry
#define P1W 0x11200
#define P2W 0x1B4D1

template <int D>
__device__ __forceinline__ int gidx(int t1, int t2, int m) {
    int a, b;
    if (D == 16) { a = 4 * t1 + (m >> 2); b = 4 * t2 + (m & 3); }
    else { a = 4 * t1 + ((P1W >> (3 * m)) & 7); b = 4 * t1 + ((P2W >> (3 * m)) & 7); }
    return pair_idx(a, b);
}

template <int DI, int DJ>
__device__ __forceinline__ void process(
    const float* __restrict__ rho, float* __restrict__ out,
    int T1, int T2, int t1, int t2, int tid,
    const float (*sV)[16], const float (*sW)[36],
    float (*bufA)[17], float (*bufB)[17])
{
    // ---- load rho block (overlaps with V/W setup; barrier comes from caller)
    #pragma unroll
    for (int e = tid; e < DI * DJ; e += 64) {
        int m = e / DJ, c = e % DJ;
        bufA[m][c] = rho[gidx<DI>(T1, T2, m) * NP + gidx<DJ>(t1, t2, c)];
    }
    __syncthreads();   // bufA + sV + sW all ready

    float (*cur)[17] = bufA;
    float (*nxt)[17] = bufB;

    // ---- LEFT: cur <- B_I * cur
    if (DI == 16) {
        const float* V1 = sV[T1 >> 2];
        const float* V2 = sV[T2 >> 2];
        #pragma unroll
        for (int e = tid; e < 16 * DJ; e += 64) {
            int m = e / DJ, c = e % DJ;
            int al = m >> 2, bp = m & 3;
            float acc = 0.f;
            #pragma unroll
            for (int ap = 0; ap < 4; ap++) acc += V1[al * 4 + ap] * cur[ap * 4 + bp][c];
            nxt[m][c] = acc;
        }
        __syncthreads();
        { float (*t)[17] = cur; cur = nxt; nxt = t; }
        #pragma unroll
        for (int e = tid; e < 16 * DJ; e += 64) {
            int m = e / DJ, c = e % DJ;
            int base = m & ~3, be = m & 3;
            float acc = 0.f;
            #pragma unroll
            for (int bp = 0; bp < 4; bp++) acc += V2[be * 4 + bp] * cur[base + bp][c];
            nxt[m][c] = acc;
        }
        __syncthreads();
        { float (*t)[17] = cur; cur = nxt; nxt = t; }
    } else {
        const float* WI = sW[T1 >> 2];
        #pragma unroll
        for (int e = tid; e < 6 * DJ; e += 64) {
            int m = e / DJ, c = e % DJ;
            float acc = 0.f;
            #pragma unroll
            for (int n = 0; n < 6; n++) acc += WI[m * 6 + n] * cur[n][c];
            nxt[m][c] = acc;
        }
        __syncthreads();
        { float (*t)[17] = cur; cur = nxt; nxt = t; }
    }

    // ---- RIGHT: cur <- cur * B_J^T
    if (DJ == 16) {
        const float* V1 = sV[t1 >> 2];
        const float* V2 = sV[t2 >> 2];
        #pragma unroll
        for (int e = tid; e < DI * 16; e += 64) {
            int m = e >> 4, c = e & 15;
            int ga = c >> 2, dp = c & 3;
            float acc = 0.f;
            #pragma unroll
            for (int gp = 0; gp < 4; gp++) acc += V1[ga * 4 + gp] * cur[m][gp * 4 + dp];
            nxt[m][c] = acc;
        }
        __syncthreads();
        { float (*t)[17] = cur; cur = nxt; nxt = t; }
        #pragma unroll
        for (int e = tid; e < DI * 16; e += 64) {
            int m = e >> 4, c = e & 15;
            int base = c & ~3, de = c & 3;
            float acc = 0.f;
            #pragma unroll
            for (int dp = 0; dp < 4; dp++) acc += V2[de * 4 + dp] * cur[m][base + dp];
            nxt[m][c] = acc;
        }
        __syncthreads();
        { float (*t)[17] = cur; cur = nxt; nxt = t; }
    } else {
        const float* WJ = sW[t1 >> 2];
        #pragma unroll
        for (int e = tid; e < DI * 6; e += 64) {
            int m = e / 6, c = e % 6;
            float acc = 0.f;
            #pragma unroll
            for (int n = 0; n < 6; n++) acc += WJ[c * 6 + n] * cur[m][n];
            nxt[m][c] = acc;
        }
        __syncthreads();
        { float (*t)[17] = cur; cur = nxt; nxt = t; }
    }

    // ---- store
    #pragma unroll
    for (int e = tid; e < DI * DJ; e += 64) {
        int m = e / DJ, c = e % DJ;
        out[gidx<DI>(T1, T2, m) * NP + gidx<DJ>(t1, t2, c)] = cur[m][c];
    }
}

__global__ void __launch_bounds__(64, 16)
rbs_pair_kernel(const float* __restrict__ rho, float* __restrict__ out,
                const float* __restrict__ thetas)
{
    __shared__ float sV[2][16];   // V_row, V_col (4x4 row-major)
    __shared__ float sW[2][36];   // Lambda^2(V) for diagonal blocks
    __shared__ float bufA[16][17], bufB[16][17];

    const int tid = threadIdx.x;
    const int I = blockIdx.x / 36, J = blockIdx.x % 36;

    int T1, T2, DI, t1, t2, DJ;
    decode_block(I, T1, T2, DI);
    decode_block(J, t1, t2, DJ);

    // ---- compose V per warp (warp 0: row params 0-5, warp 1: col params 6-11)
    {
        const int reg = tid >> 5;
        float cs[6], sn[6];
        #pragma unroll
        for (int p = 0; p < 6; p++)
            sincosf(__ldg(thetas + reg * 6 + p), &sn[p], &cs[p]);

        float v[4][4] = {{1,0,0,0},{0,1,0,0},{0,0,1,0},{0,0,0,1}};
        const int jseq[6] = {0, 1, 0, 2, 1, 0};   // fixed pyramid order
        #pragma unroll
        for (int gi = 0; gi < 6; gi++) {
            const int j = jseq[gi];
            const float c = cs[gi], s = sn[gi];
            #pragma unroll
            for (int k = 0; k < 4; k++) {
                float a = v[j][k], b = v[j + 1][k];
                v[j][k]     = c * a + s * b;
                v[j + 1][k] = c * b - s * a;
            }
        }
        if ((tid & 31) == 0) {
            #pragma unroll
            for (int r = 0; r < 4; r++)
                #pragma unroll
                for (int c = 0; c < 4; c++) sV[reg][r * 4 + c] = v[r][c];
        }
    }
    __syncthreads();

    // ---- W = Lambda^2(V), thread-sliced (72 entries)
    for (int e = tid; e < 72; e += 64) {
        int side = e / 36, mn = e % 36, m = mn / 6, n = mn % 6;
        int a = (P1W >> (3 * m)) & 7, b = (P2W >> (3 * m)) & 7;
        int g = (P1W >> (3 * n)) & 7, d = (P2W >> (3 * n)) & 7;
        const float* V = sV[side];
        sW[side][mn] = V[a * 4 + g] * V[b * 4 + d] - V[a * 4 + d] * V[b * 4 + g];
    }
    // NOTE: the __syncthreads inside process() (after the rho load) also
    // publishes sW before any stage reads it.

    if (DI == 16) {
        if (DJ == 16) process<16,16>(rho, out, T1, T2, t1, t2, tid, sV, sW, bufA, bufB);
        else          process<16, 6>(rho, out, T1, T2, t1, t2, tid, sV, sW, bufA, bufB);
    } else {
        if (DJ == 16) process< 6,16>(rho, out, T1, T2, t1, t2, tid, sV, sW, bufA, bufB);
        else          process< 6, 6>(rho, out, T1, T2, t1, t2, tid, sV, sW, bufA, bufB);
    }
}

extern "C" void kernel_launch(void* const* d_in, const int* in_sizes, int n_in,
                              void* d_out, int out_size) {
    // metadata order: rho, thetas, A_stack, B_stack, C_stack, u_idx, p_idx
    const float* rho    = (const float*)d_in[0];
    const float* thetas = (const float*)d_in[1];
    float* out = (float*)d_out;

    rbs_pair_kernel<<<36 * 36, 64>>>(rho, out, thetas);
}